// round 1
// baseline (speedup 1.0000x reference)
#include <cuda_runtime.h>

#define MAX_N   100000
#define FEAT    128
#define OUTF    32

// Scratch (no cudaMalloc allowed)
__device__ float g_deg_src[MAX_N];
__device__ float g_deg_dst[MAX_N];
__device__ float g_tmp[(size_t)MAX_N * OUTF];

// ---------------------------------------------------------------------------
// 1) zero output + degree arrays (out is poisoned 0xAA before timing, and the
//    graph replays, so every launch must re-zero)
// ---------------------------------------------------------------------------
__global__ void init_kernel(float* __restrict__ out, int n_nodes, int out_elems) {
    int i = blockIdx.x * blockDim.x + threadIdx.x;
    if (i < out_elems) out[i] = 0.0f;
    if (i < n_nodes) {
        g_deg_src[i] = 0.0f;
        g_deg_dst[i] = 0.0f;
    }
}

// ---------------------------------------------------------------------------
// 2) degree histograms (fp32 atomics; counts are small integers -> exact)
// ---------------------------------------------------------------------------
__global__ void degree_kernel(const int* __restrict__ src,
                              const int* __restrict__ dst, int E) {
    int i = blockIdx.x * blockDim.x + threadIdx.x;
    if (i < E) {
        atomicAdd(&g_deg_src[src[i]], 1.0f);
        atomicAdd(&g_deg_dst[dst[i]], 1.0f);
    }
}

// ---------------------------------------------------------------------------
// 3) fused src-scale + GEMM: g_tmp[row] = (feat[row] * outdeg^-1/2) @ W
//    warp-per-row, lane-per-output-col; W staged in shared (conflict-free:
//    sw[k][lane] has stride-1 across lanes).
// ---------------------------------------------------------------------------
__global__ void gemm_kernel(const float* __restrict__ feat,
                            const float* __restrict__ W, int n_nodes) {
    __shared__ float sw[FEAT][OUTF];
    int tid = threadIdx.x;
    for (int i = tid; i < FEAT * OUTF; i += blockDim.x) {
        sw[i / OUTF][i % OUTF] = W[i];
    }
    __syncthreads();

    int warp = tid >> 5;
    int lane = tid & 31;
    int row  = blockIdx.x * 8 + warp;
    if (row >= n_nodes) return;

    float scale = rsqrtf(fmaxf(g_deg_src[row], 1.0f));
    const float4* f4 = reinterpret_cast<const float4*>(feat + (size_t)row * FEAT);

    float acc = 0.0f;
#pragma unroll
    for (int k4 = 0; k4 < FEAT / 4; ++k4) {
        float4 f = f4[k4];            // uniform across lanes -> broadcast
        int k = k4 * 4;
        acc = fmaf(f.x, sw[k + 0][lane], acc);
        acc = fmaf(f.y, sw[k + 1][lane], acc);
        acc = fmaf(f.z, sw[k + 2][lane], acc);
        acc = fmaf(f.w, sw[k + 3][lane], acc);
    }
    g_tmp[(size_t)row * OUTF + lane] = acc * scale;
}

// ---------------------------------------------------------------------------
// 4) SpMM scatter: warp-per-edge (x4 for MLP), lane-per-float.
//    Gather is one coalesced 128B line per edge; scatter is 32 contiguous
//    fp32 REDG into the (L2-resident) output.
// ---------------------------------------------------------------------------
#define EDGES_PER_WARP 4
__global__ void scatter_kernel(const int* __restrict__ src,
                               const int* __restrict__ dst,
                               float* __restrict__ out, int E) {
    int warp_global = (blockIdx.x * blockDim.x + threadIdx.x) >> 5;
    int lane = threadIdx.x & 31;
    int base = warp_global * EDGES_PER_WARP;

#pragma unroll
    for (int j = 0; j < EDGES_PER_WARP; ++j) {
        int e = base + j;
        if (e < E) {
            int s = __ldg(&src[e]);
            int d = __ldg(&dst[e]);
            float v = g_tmp[(size_t)s * OUTF + lane];
            atomicAdd(&out[(size_t)d * OUTF + lane], v);
        }
    }
}

// ---------------------------------------------------------------------------
// 5) dst-side scale: out[row] *= indeg^-1/2
// ---------------------------------------------------------------------------
__global__ void final_scale_kernel(float* __restrict__ out, int out_elems) {
    int i = blockIdx.x * blockDim.x + threadIdx.x;
    if (i < out_elems) {
        out[i] *= rsqrtf(fmaxf(g_deg_dst[i >> 5], 1.0f));  // OUTF == 32
    }
}

// ---------------------------------------------------------------------------
extern "C" void kernel_launch(void* const* d_in, const int* in_sizes, int n_in,
                              void* d_out, int out_size) {
    const float* feat = (const float*)d_in[0];
    const int*   src  = (const int*)d_in[1];
    const int*   dst  = (const int*)d_in[2];
    const float* W    = (const float*)d_in[3];
    float* out = (float*)d_out;

    int n_nodes   = in_sizes[0] / FEAT;
    int E         = in_sizes[1];
    int out_elems = out_size;

    // 1) init
    {
        int n = out_elems > n_nodes ? out_elems : n_nodes;
        init_kernel<<<(n + 255) / 256, 256>>>(out, n_nodes, out_elems);
    }
    // 2) degrees
    degree_kernel<<<(E + 255) / 256, 256>>>(src, dst, E);
    // 3) scaled GEMM into g_tmp
    gemm_kernel<<<(n_nodes + 7) / 8, 256>>>(feat, W, n_nodes);
    // 4) edge scatter
    {
        int warps = (E + EDGES_PER_WARP - 1) / EDGES_PER_WARP;
        int threads = warps * 32;
        scatter_kernel<<<(threads + 255) / 256, 256>>>(src, dst, out, E);
    }
    // 5) final scale
    final_scale_kernel<<<(out_elems + 255) / 256, 256>>>(out, out_elems);
}

// round 2
// speedup vs baseline: 1.3404x; 1.3404x over previous
#include <cuda_runtime.h>

#define FEAT   128
#define OUTF   32
#define MAX_N  100000
#define MAX_E  1600000
#define SCAN_B 1024

// Scratch (no cudaMalloc allowed)
__device__ int   g_deg_src[MAX_N];
__device__ int   g_deg_dst[MAX_N];
__device__ int   g_row_off[MAX_N + 1];
__device__ int   g_cursor[MAX_N];
__device__ int   g_csr_src[MAX_E];
__device__ int   g_part[1024];
__device__ float g_tmp[(size_t)MAX_N * OUTF];

// ---------------------------------------------------------------------------
// 1) zero degree arrays (graph replays -> must re-zero every launch)
// ---------------------------------------------------------------------------
__global__ void init_kernel(int n_nodes) {
    int i = blockIdx.x * blockDim.x + threadIdx.x;
    if (i < n_nodes) {
        g_deg_src[i] = 0;
        g_deg_dst[i] = 0;
    }
}

// ---------------------------------------------------------------------------
// 2) degree histograms (int atomics, exact)
// ---------------------------------------------------------------------------
__global__ void degree_kernel(const int* __restrict__ src,
                              const int* __restrict__ dst, int E) {
    int i = blockIdx.x * blockDim.x + threadIdx.x;
    if (i < E) {
        atomicAdd(&g_deg_src[src[i]], 1);
        atomicAdd(&g_deg_dst[dst[i]], 1);
    }
}

// ---------------------------------------------------------------------------
// 3) exclusive scan of g_deg_dst -> g_row_off (3 kernels)
// ---------------------------------------------------------------------------
__global__ void scan1_kernel(int n) {            // per-block sums
    __shared__ int sh[SCAN_B];
    int tid = threadIdx.x;
    int i = blockIdx.x * SCAN_B + tid;
    sh[tid] = (i < n) ? g_deg_dst[i] : 0;
    __syncthreads();
    for (int s = SCAN_B / 2; s > 0; s >>= 1) {
        if (tid < s) sh[tid] += sh[tid + s];
        __syncthreads();
    }
    if (tid == 0) g_part[blockIdx.x] = sh[0];
}

__global__ void scan2_kernel(int nb) {           // exclusive scan of partials
    __shared__ int sh[SCAN_B];
    int tid = threadIdx.x;
    int v = (tid < nb) ? g_part[tid] : 0;
    sh[tid] = v;
    __syncthreads();
    for (int off = 1; off < SCAN_B; off <<= 1) {
        int t = (tid >= off) ? sh[tid - off] : 0;
        __syncthreads();
        sh[tid] += t;
        __syncthreads();
    }
    g_part[tid] = sh[tid] - v;                   // exclusive
}

__global__ void scan3_kernel(int n) {            // in-block scan + offset
    __shared__ int sh[SCAN_B];
    int tid = threadIdx.x;
    int i = blockIdx.x * SCAN_B + tid;
    int v = (i < n) ? g_deg_dst[i] : 0;
    sh[tid] = v;
    __syncthreads();
    for (int off = 1; off < SCAN_B; off <<= 1) {
        int t = (tid >= off) ? sh[tid - off] : 0;
        __syncthreads();
        sh[tid] += t;
        __syncthreads();
    }
    int excl = sh[tid] - v + g_part[blockIdx.x];
    if (i < n) {
        g_row_off[i] = excl;
        g_cursor[i]  = excl;
        if (i == n - 1) g_row_off[n] = excl + v;
    }
}

// ---------------------------------------------------------------------------
// 4) CSR fill: counting-sort edges by dst (int atomics on cursors)
// ---------------------------------------------------------------------------
__global__ void fill_kernel(const int* __restrict__ src,
                            const int* __restrict__ dst, int E) {
    int i = blockIdx.x * blockDim.x + threadIdx.x;
    if (i < E) {
        int pos = atomicAdd(&g_cursor[dst[i]], 1);
        g_csr_src[pos] = src[i];
    }
}

// ---------------------------------------------------------------------------
// 5) fused src-scale + GEMM: g_tmp[row] = (feat[row]*outdeg^-1/2) @ W
//    32 rows/block, 4 rows/warp, feat + W staged in shared.
//    FMA-pipe bound (~409.6M FMAs total).
// ---------------------------------------------------------------------------
__global__ void gemm_kernel(const float* __restrict__ feat,
                            const float* __restrict__ W, int n_nodes) {
    __shared__ float sw[FEAT][OUTF];     // 16 KB
    __shared__ float sf[32 * FEAT];      // 16 KB
    int tid = threadIdx.x;
    int R0  = blockIdx.x * 32;

    // stage W (coalesced)
    const float4* w4 = reinterpret_cast<const float4*>(W);
    float4* sw4 = reinterpret_cast<float4*>(&sw[0][0]);
    for (int i = tid; i < FEAT * OUTF / 4; i += 256) sw4[i] = w4[i];

    // stage feat rows [R0, R0+32) (coalesced; guard partial tail block)
    const float4* f4 = reinterpret_cast<const float4*>(feat + (size_t)R0 * FEAT);
    float4* sf4 = reinterpret_cast<float4*>(sf);
    int lim4 = (n_nodes - R0 >= 32) ? (32 * FEAT / 4)
                                    : ((n_nodes > R0 ? (n_nodes - R0) : 0) * FEAT / 4);
    for (int i = tid; i < lim4; i += 256) sf4[i] = f4[i];
    __syncthreads();

    int warp = tid >> 5;
    int lane = tid & 31;
    int lr0  = warp * 4;                 // local row base (0..28)

    float acc[4] = {0.f, 0.f, 0.f, 0.f};
    const float4* sfr = reinterpret_cast<const float4*>(sf);

#pragma unroll
    for (int k4 = 0; k4 < FEAT / 4; ++k4) {
#pragma unroll
        for (int r = 0; r < 4; ++r) {
            if (R0 + lr0 + r < n_nodes) {
                float4 f = sfr[(lr0 + r) * (FEAT / 4) + k4];   // broadcast
                int k = k4 * 4;
                acc[r] = fmaf(f.x, sw[k + 0][lane], acc[r]);
                acc[r] = fmaf(f.y, sw[k + 1][lane], acc[r]);
                acc[r] = fmaf(f.z, sw[k + 2][lane], acc[r]);
                acc[r] = fmaf(f.w, sw[k + 3][lane], acc[r]);
            }
        }
    }
#pragma unroll
    for (int r = 0; r < 4; ++r) {
        int gr = R0 + lr0 + r;
        if (gr < n_nodes) {
            float scale = rsqrtf(fmaxf((float)g_deg_src[gr], 1.0f));
            g_tmp[(size_t)gr * OUTF + lane] = acc[r] * scale;
        }
    }
}

// ---------------------------------------------------------------------------
// 6) gather-sum: warp-per-dst, lane-per-col. No atomics; edges broadcast
//    via shfl; fuses in_deg^-0.5 (= row_off diff). Writes every out row.
// ---------------------------------------------------------------------------
__global__ void gather_kernel(float* __restrict__ out, int n_nodes) {
    int warp_global = (blockIdx.x * blockDim.x + threadIdx.x) >> 5;
    int lane = threadIdx.x & 31;
    int d = warp_global;
    if (d >= n_nodes) return;

    int beg = g_row_off[d];
    int end = g_row_off[d + 1];

    float acc = 0.0f;
    for (int base = beg; base < end; base += 32) {
        int idx = base + lane;
        int s = (idx < end) ? g_csr_src[idx] : 0;
        int cnt = min(32, end - base);
        for (int j = 0; j < cnt; ++j) {
            int sj = __shfl_sync(0xffffffffu, s, j);
            acc += g_tmp[(size_t)sj * OUTF + lane];
        }
    }
    float scale = rsqrtf(fmaxf((float)(end - beg), 1.0f));
    out[(size_t)d * OUTF + lane] = acc * scale;
}

// ---------------------------------------------------------------------------
extern "C" void kernel_launch(void* const* d_in, const int* in_sizes, int n_in,
                              void* d_out, int out_size) {
    const float* feat = (const float*)d_in[0];
    const int*   src  = (const int*)d_in[1];
    const int*   dst  = (const int*)d_in[2];
    const float* W    = (const float*)d_in[3];
    float* out = (float*)d_out;

    int n_nodes = in_sizes[0] / FEAT;
    int E       = in_sizes[1];
    int nb      = (n_nodes + SCAN_B - 1) / SCAN_B;

    init_kernel<<<(n_nodes + 255) / 256, 256>>>(n_nodes);
    degree_kernel<<<(E + 255) / 256, 256>>>(src, dst, E);
    scan1_kernel<<<nb, SCAN_B>>>(n_nodes);
    scan2_kernel<<<1, SCAN_B>>>(nb);
    scan3_kernel<<<nb, SCAN_B>>>(n_nodes);
    fill_kernel<<<(E + 255) / 256, 256>>>(src, dst, E);
    gemm_kernel<<<(n_nodes + 31) / 32, 256>>>(feat, W, n_nodes);
    {
        int warps = n_nodes;                     // one warp per dst node
        int threads = 256;
        int blocks = (warps * 32 + threads - 1) / threads;
        gather_kernel<<<blocks, threads>>>(out, n_nodes);
    }
}

// round 3
// speedup vs baseline: 1.7986x; 1.3419x over previous
#include <cuda_runtime.h>

#define FEAT   128
#define OUTF   32
#define MAX_N  100000
#define MAX_E  1600000
#define SCAN_B 1024
#define RPB    64            // gemm rows per block

// Scratch (no cudaMalloc allowed)
__device__ int   g_deg_src[MAX_N];
__device__ int   g_deg_dst[MAX_N];
__device__ int   g_row_off[MAX_N + 1];
__device__ int   g_cursor[MAX_N];
__device__ int   g_csr_src[MAX_E];
__device__ int   g_blk_sum[128];
__device__ int   g_blk_flag[128];
__device__ float g_tmp[(size_t)MAX_N * OUTF];

// ---------------------------------------------------------------------------
// 1) zero degree arrays + scan flags (graph replays -> re-zero every launch)
// ---------------------------------------------------------------------------
__global__ void init_kernel(int n_nodes) {
    int i = blockIdx.x * blockDim.x + threadIdx.x;
    if (i < n_nodes) {
        g_deg_src[i] = 0;
        g_deg_dst[i] = 0;
    }
    if (i < 128) g_blk_flag[i] = 0;
}

// ---------------------------------------------------------------------------
// 2) degree histograms (int atomics, exact); int4 edge loads
// ---------------------------------------------------------------------------
__global__ void degree_kernel(const int* __restrict__ src,
                              const int* __restrict__ dst, int E) {
    int i = blockIdx.x * blockDim.x + threadIdx.x;
    int e0 = i * 4;
    if (e0 + 3 < E) {
        int4 s = reinterpret_cast<const int4*>(src)[i];
        int4 d = reinterpret_cast<const int4*>(dst)[i];
        atomicAdd(&g_deg_src[s.x], 1); atomicAdd(&g_deg_dst[d.x], 1);
        atomicAdd(&g_deg_src[s.y], 1); atomicAdd(&g_deg_dst[d.y], 1);
        atomicAdd(&g_deg_src[s.z], 1); atomicAdd(&g_deg_dst[d.z], 1);
        atomicAdd(&g_deg_src[s.w], 1); atomicAdd(&g_deg_dst[d.w], 1);
    } else {
        for (int e = e0; e < E; ++e) {
            atomicAdd(&g_deg_src[src[e]], 1);
            atomicAdd(&g_deg_dst[dst[e]], 1);
        }
    }
}

// ---------------------------------------------------------------------------
// 3) single-kernel exclusive scan of g_deg_dst -> g_row_off / g_cursor.
//    Decoupled lookback: each block publishes its local sum, then sums all
//    lower-bid partials (blocks publish before spinning; lower bids are
//    scheduled first, so this cannot deadlock).
// ---------------------------------------------------------------------------
__global__ void scan_kernel(int n) {
    __shared__ int sh[SCAN_B];
    __shared__ int red[SCAN_B];
    int tid = threadIdx.x;
    int b   = blockIdx.x;
    int i   = b * SCAN_B + tid;

    int v = (i < n) ? g_deg_dst[i] : 0;
    sh[tid] = v;
    __syncthreads();
    // inclusive scan (Hillis-Steele)
    for (int off = 1; off < SCAN_B; off <<= 1) {
        int t = (tid >= off) ? sh[tid - off] : 0;
        __syncthreads();
        sh[tid] += t;
        __syncthreads();
    }

    // publish local total
    if (tid == 0) {
        g_blk_sum[b] = sh[SCAN_B - 1];
        __threadfence();
        atomicExch(&g_blk_flag[b], 1);
    }

    // lookback: sum partials of blocks [0, b)
    int partial = 0;
    if (tid < b) {
        while (atomicAdd(&g_blk_flag[tid], 0) == 0) { }
        partial = atomicAdd(&g_blk_sum[tid], 0);
    }
    red[tid] = partial;
    __syncthreads();
    for (int s = SCAN_B / 2; s > 0; s >>= 1) {
        if (tid < s) red[tid] += red[tid + s];
        __syncthreads();
    }
    int prev = red[0];

    int excl = prev + sh[tid] - v;
    if (i < n) {
        g_row_off[i] = excl;
        g_cursor[i]  = excl;
        if (i == n - 1) g_row_off[n] = excl + v;
    }
}

// ---------------------------------------------------------------------------
// 4) CSR fill: counting-sort edges by dst; int4 edge loads
// ---------------------------------------------------------------------------
__global__ void fill_kernel(const int* __restrict__ src,
                            const int* __restrict__ dst, int E) {
    int i = blockIdx.x * blockDim.x + threadIdx.x;
    int e0 = i * 4;
    if (e0 + 3 < E) {
        int4 s = reinterpret_cast<const int4*>(src)[i];
        int4 d = reinterpret_cast<const int4*>(dst)[i];
        g_csr_src[atomicAdd(&g_cursor[d.x], 1)] = s.x;
        g_csr_src[atomicAdd(&g_cursor[d.y], 1)] = s.y;
        g_csr_src[atomicAdd(&g_cursor[d.z], 1)] = s.z;
        g_csr_src[atomicAdd(&g_cursor[d.w], 1)] = s.w;
    } else {
        for (int e = e0; e < E; ++e)
            g_csr_src[atomicAdd(&g_cursor[dst[e]], 1)] = src[e];
    }
}

// ---------------------------------------------------------------------------
// 5) fused src-scale + GEMM: g_tmp[row] = (feat[row]*outdeg^-1/2) @ W
//    64 rows/block, 8 rows/warp. FFMA-bound floor ~22us.
// ---------------------------------------------------------------------------
__global__ void __launch_bounds__(256, 4)
gemm_kernel(const float* __restrict__ feat, const float* __restrict__ W,
            int n_nodes) {
    __shared__ float sw[FEAT][OUTF];       // 16 KB
    __shared__ float sf[RPB * FEAT];       // 32 KB
    int tid = threadIdx.x;
    int R0  = blockIdx.x * RPB;
    int rows = n_nodes - R0;
    if (rows > RPB) rows = RPB;

    // stage W (coalesced): 1024 float4
    const float4* w4 = reinterpret_cast<const float4*>(W);
    float4* sw4 = reinterpret_cast<float4*>(&sw[0][0]);
#pragma unroll
    for (int i = 0; i < FEAT * OUTF / 4 / 256; ++i)
        sw4[i * 256 + tid] = w4[i * 256 + tid];

    // stage feat rows (coalesced): rows*32 float4
    const float4* f4 = reinterpret_cast<const float4*>(feat + (size_t)R0 * FEAT);
    float4* sf4 = reinterpret_cast<float4*>(sf);
    int lim4 = rows * (FEAT / 4);
    for (int i = tid; i < lim4; i += 256) sf4[i] = f4[i];
    __syncthreads();

    int warp = tid >> 5;
    int lane = tid & 31;
    int lr0  = warp * 8;

    float acc[8] = {0.f, 0.f, 0.f, 0.f, 0.f, 0.f, 0.f, 0.f};
    const float4* sfr = reinterpret_cast<const float4*>(sf);

    if (rows == RPB) {                     // fast path: no guards
#pragma unroll
        for (int k4 = 0; k4 < FEAT / 4; ++k4) {
            int k = k4 * 4;
            float w0 = sw[k + 0][lane], w1 = sw[k + 1][lane];
            float w2 = sw[k + 2][lane], w3 = sw[k + 3][lane];
#pragma unroll
            for (int r = 0; r < 8; ++r) {
                float4 f = sfr[(lr0 + r) * (FEAT / 4) + k4];   // broadcast
                acc[r] = fmaf(f.x, w0, acc[r]);
                acc[r] = fmaf(f.y, w1, acc[r]);
                acc[r] = fmaf(f.z, w2, acc[r]);
                acc[r] = fmaf(f.w, w3, acc[r]);
            }
        }
#pragma unroll
        for (int r = 0; r < 8; ++r) {
            int gr = R0 + lr0 + r;
            float scale = rsqrtf(fmaxf((float)g_deg_src[gr], 1.0f));
            g_tmp[(size_t)gr * OUTF + lane] = acc[r] * scale;
        }
    } else {                               // tail block (1 of 1563)
        for (int k4 = 0; k4 < FEAT / 4; ++k4) {
            int k = k4 * 4;
            float w0 = sw[k + 0][lane], w1 = sw[k + 1][lane];
            float w2 = sw[k + 2][lane], w3 = sw[k + 3][lane];
            for (int r = 0; r < 8; ++r) {
                if (lr0 + r < rows) {
                    float4 f = sfr[(lr0 + r) * (FEAT / 4) + k4];
                    acc[r] = fmaf(f.x, w0, acc[r]);
                    acc[r] = fmaf(f.y, w1, acc[r]);
                    acc[r] = fmaf(f.z, w2, acc[r]);
                    acc[r] = fmaf(f.w, w3, acc[r]);
                }
            }
        }
        for (int r = 0; r < 8; ++r) {
            int gr = R0 + lr0 + r;
            if (lr0 + r < rows) {
                float scale = rsqrtf(fmaxf((float)g_deg_src[gr], 1.0f));
                g_tmp[(size_t)gr * OUTF + lane] = acc[r] * scale;
            }
        }
    }
}

// ---------------------------------------------------------------------------
// 6) gather-sum: warp-per-dst. Lane group g=lane>>3 handles edge base+g;
//    8 lanes x float4 cover the 32-col row. Unroll x2 -> MLP 2/lane.
//    Final cross-group shfl reduce; fused in_deg^-0.5.
// ---------------------------------------------------------------------------
__global__ void gather_kernel(float* __restrict__ out, int n_nodes) {
    int warp_global = (blockIdx.x * blockDim.x + threadIdx.x) >> 5;
    if (warp_global >= n_nodes) return;
    int lane = threadIdx.x & 31;
    int g = lane >> 3;                     // edge slot 0..3
    int c = lane & 7;                      // float4 column 0..7

    int beg = g_row_off[warp_global];
    int end = g_row_off[warp_global + 1];

    const float4* tmp4 = reinterpret_cast<const float4*>(g_tmp);
    float4 acc = make_float4(0.f, 0.f, 0.f, 0.f);

    for (int base = beg; base < end; base += 8) {
        int e0 = base + g;
        int e1 = base + 4 + g;
        float4 v0 = make_float4(0.f, 0.f, 0.f, 0.f);
        float4 v1 = make_float4(0.f, 0.f, 0.f, 0.f);
        if (e0 < end) {
            int s = __ldg(&g_csr_src[e0]);
            v0 = tmp4[(size_t)s * 8 + c];
        }
        if (e1 < end) {
            int s = __ldg(&g_csr_src[e1]);
            v1 = tmp4[(size_t)s * 8 + c];
        }
        acc.x += v0.x + v1.x;
        acc.y += v0.y + v1.y;
        acc.z += v0.z + v1.z;
        acc.w += v0.w + v1.w;
    }

    // reduce across the 4 lane groups (xor 8, then 16)
#pragma unroll
    for (int off = 8; off < 32; off <<= 1) {
        acc.x += __shfl_xor_sync(0xffffffffu, acc.x, off);
        acc.y += __shfl_xor_sync(0xffffffffu, acc.y, off);
        acc.z += __shfl_xor_sync(0xffffffffu, acc.z, off);
        acc.w += __shfl_xor_sync(0xffffffffu, acc.w, off);
    }

    if (lane < 8) {
        float scale = rsqrtf(fmaxf((float)(end - beg), 1.0f));
        float4 o = make_float4(acc.x * scale, acc.y * scale,
                               acc.z * scale, acc.w * scale);
        reinterpret_cast<float4*>(out)[(size_t)warp_global * 8 + lane] = o;
    }
}

// ---------------------------------------------------------------------------
extern "C" void kernel_launch(void* const* d_in, const int* in_sizes, int n_in,
                              void* d_out, int out_size) {
    const float* feat = (const float*)d_in[0];
    const int*   src  = (const int*)d_in[1];
    const int*   dst  = (const int*)d_in[2];
    const float* W    = (const float*)d_in[3];
    float* out = (float*)d_out;

    int n_nodes = in_sizes[0] / FEAT;
    int E       = in_sizes[1];
    int nb      = (n_nodes + SCAN_B - 1) / SCAN_B;
    int eth     = (E + 3) / 4;             // edge-quad threads

    init_kernel<<<(n_nodes + 255) / 256, 256>>>(n_nodes);
    degree_kernel<<<(eth + 255) / 256, 256>>>(src, dst, E);
    scan_kernel<<<nb, SCAN_B>>>(n_nodes);
    fill_kernel<<<(eth + 255) / 256, 256>>>(src, dst, E);
    gemm_kernel<<<(n_nodes + RPB - 1) / RPB, 256>>>(feat, W, n_nodes);
    gather_kernel<<<(n_nodes * 32 + 255) / 256, 256>>>(out, n_nodes);
}

// round 4
// speedup vs baseline: 1.8255x; 1.0150x over previous
#include <cuda_runtime.h>

#define FEAT   128
#define OUTF   32
#define MAX_N  100000
#define MAX_E  1600000
#define SCAN_B 1024
#define RPB    64            // gemm rows per block

// Scratch (no cudaMalloc allowed)
__device__ int   g_deg_src[MAX_N];
__device__ int   g_deg_dst[MAX_N];
__device__ int   g_row_off[MAX_N + 1];
__device__ int   g_cursor[MAX_N];
__device__ int   g_csr_src[MAX_E];
__device__ int   g_blk_sum[128];
__device__ int   g_blk_flag[128];
__device__ float g_tmp[(size_t)MAX_N * OUTF];

// ---------------------------------------------------------------------------
// 1) zero degree arrays + scan flags (graph replays -> re-zero every launch)
// ---------------------------------------------------------------------------
__global__ void init_kernel(int n_nodes) {
    int i = blockIdx.x * blockDim.x + threadIdx.x;
    if (i < n_nodes) {
        g_deg_src[i] = 0;
        g_deg_dst[i] = 0;
    }
    if (i < 128) g_blk_flag[i] = 0;
}

// ---------------------------------------------------------------------------
// 2) degree histograms: 8 edges/thread, 16 independent no-return REDs
// ---------------------------------------------------------------------------
__global__ void degree_kernel(const int* __restrict__ src,
                              const int* __restrict__ dst, int E) {
    int i = blockIdx.x * blockDim.x + threadIdx.x;
    int e0 = i * 8;
    if (e0 + 7 < E) {
        const int4* s4 = reinterpret_cast<const int4*>(src);
        const int4* d4 = reinterpret_cast<const int4*>(dst);
        int4 sa = s4[i * 2], sb = s4[i * 2 + 1];
        int4 da = d4[i * 2], db = d4[i * 2 + 1];
        atomicAdd(&g_deg_src[sa.x], 1); atomicAdd(&g_deg_src[sa.y], 1);
        atomicAdd(&g_deg_src[sa.z], 1); atomicAdd(&g_deg_src[sa.w], 1);
        atomicAdd(&g_deg_src[sb.x], 1); atomicAdd(&g_deg_src[sb.y], 1);
        atomicAdd(&g_deg_src[sb.z], 1); atomicAdd(&g_deg_src[sb.w], 1);
        atomicAdd(&g_deg_dst[da.x], 1); atomicAdd(&g_deg_dst[da.y], 1);
        atomicAdd(&g_deg_dst[da.z], 1); atomicAdd(&g_deg_dst[da.w], 1);
        atomicAdd(&g_deg_dst[db.x], 1); atomicAdd(&g_deg_dst[db.y], 1);
        atomicAdd(&g_deg_dst[db.z], 1); atomicAdd(&g_deg_dst[db.w], 1);
    } else {
        for (int e = e0; e < E; ++e) {
            atomicAdd(&g_deg_src[src[e]], 1);
            atomicAdd(&g_deg_dst[dst[e]], 1);
        }
    }
}

// ---------------------------------------------------------------------------
// 3) single-kernel exclusive scan of g_deg_dst (decoupled lookback; lower
//    bids publish before higher bids spin -> no deadlock)
// ---------------------------------------------------------------------------
__global__ void scan_kernel(int n) {
    __shared__ int sh[SCAN_B];
    __shared__ int red[SCAN_B];
    int tid = threadIdx.x;
    int b   = blockIdx.x;
    int i   = b * SCAN_B + tid;

    int v = (i < n) ? g_deg_dst[i] : 0;
    sh[tid] = v;
    __syncthreads();
    for (int off = 1; off < SCAN_B; off <<= 1) {
        int t = (tid >= off) ? sh[tid - off] : 0;
        __syncthreads();
        sh[tid] += t;
        __syncthreads();
    }

    if (tid == 0) {
        g_blk_sum[b] = sh[SCAN_B - 1];
        __threadfence();
        atomicExch(&g_blk_flag[b], 1);
    }

    int partial = 0;
    if (tid < b) {
        while (atomicAdd(&g_blk_flag[tid], 0) == 0) { }
        partial = atomicAdd(&g_blk_sum[tid], 0);
    }
    red[tid] = partial;
    __syncthreads();
    for (int s = SCAN_B / 2; s > 0; s >>= 1) {
        if (tid < s) red[tid] += red[tid + s];
        __syncthreads();
    }
    int prev = red[0];

    int excl = prev + sh[tid] - v;
    if (i < n) {
        g_row_off[i] = excl;
        g_cursor[i]  = excl;
        if (i == n - 1) g_row_off[n] = excl + v;
    }
}

// ---------------------------------------------------------------------------
// 4) CSR fill: 8 edges/thread, two-phase (8 atomics in flight, then 8 stores)
// ---------------------------------------------------------------------------
__global__ void fill_kernel(const int* __restrict__ src,
                            const int* __restrict__ dst, int E) {
    int i = blockIdx.x * blockDim.x + threadIdx.x;
    int e0 = i * 8;
    if (e0 + 7 < E) {
        const int4* s4 = reinterpret_cast<const int4*>(src);
        const int4* d4 = reinterpret_cast<const int4*>(dst);
        int4 sa = s4[i * 2], sb = s4[i * 2 + 1];
        int4 da = d4[i * 2], db = d4[i * 2 + 1];
        int s[8] = {sa.x, sa.y, sa.z, sa.w, sb.x, sb.y, sb.z, sb.w};
        int d[8] = {da.x, da.y, da.z, da.w, db.x, db.y, db.z, db.w};
        int pos[8];
#pragma unroll
        for (int j = 0; j < 8; ++j) pos[j] = atomicAdd(&g_cursor[d[j]], 1);
#pragma unroll
        for (int j = 0; j < 8; ++j) g_csr_src[pos[j]] = s[j];
    } else {
        for (int e = e0; e < E; ++e)
            g_csr_src[atomicAdd(&g_cursor[dst[e]], 1)] = src[e];
    }
}

// ---------------------------------------------------------------------------
// 5) fused src-scale + GEMM (runs on a forked stream, hidden behind scan+fill)
// ---------------------------------------------------------------------------
__global__ void __launch_bounds__(256, 4)
gemm_kernel(const float* __restrict__ feat, const float* __restrict__ W,
            int n_nodes) {
    __shared__ float sw[FEAT][OUTF];       // 16 KB
    __shared__ float sf[RPB * FEAT];       // 32 KB
    int tid = threadIdx.x;
    int R0  = blockIdx.x * RPB;
    int rows = n_nodes - R0;
    if (rows > RPB) rows = RPB;

    const float4* w4 = reinterpret_cast<const float4*>(W);
    float4* sw4 = reinterpret_cast<float4*>(&sw[0][0]);
#pragma unroll
    for (int i = 0; i < FEAT * OUTF / 4 / 256; ++i)
        sw4[i * 256 + tid] = w4[i * 256 + tid];

    const float4* f4 = reinterpret_cast<const float4*>(feat + (size_t)R0 * FEAT);
    float4* sf4 = reinterpret_cast<float4*>(sf);
    int lim4 = rows * (FEAT / 4);
    for (int i = tid; i < lim4; i += 256) sf4[i] = f4[i];
    __syncthreads();

    int warp = tid >> 5;
    int lane = tid & 31;
    int lr0  = warp * 8;

    float acc[8] = {0.f, 0.f, 0.f, 0.f, 0.f, 0.f, 0.f, 0.f};
    const float4* sfr = reinterpret_cast<const float4*>(sf);

    if (rows == RPB) {
#pragma unroll
        for (int k4 = 0; k4 < FEAT / 4; ++k4) {
            int k = k4 * 4;
            float w0 = sw[k + 0][lane], w1 = sw[k + 1][lane];
            float w2 = sw[k + 2][lane], w3 = sw[k + 3][lane];
#pragma unroll
            for (int r = 0; r < 8; ++r) {
                float4 f = sfr[(lr0 + r) * (FEAT / 4) + k4];
                acc[r] = fmaf(f.x, w0, acc[r]);
                acc[r] = fmaf(f.y, w1, acc[r]);
                acc[r] = fmaf(f.z, w2, acc[r]);
                acc[r] = fmaf(f.w, w3, acc[r]);
            }
        }
#pragma unroll
        for (int r = 0; r < 8; ++r) {
            int gr = R0 + lr0 + r;
            float scale = rsqrtf(fmaxf((float)g_deg_src[gr], 1.0f));
            g_tmp[(size_t)gr * OUTF + lane] = acc[r] * scale;
        }
    } else {
        for (int k4 = 0; k4 < FEAT / 4; ++k4) {
            int k = k4 * 4;
            float w0 = sw[k + 0][lane], w1 = sw[k + 1][lane];
            float w2 = sw[k + 2][lane], w3 = sw[k + 3][lane];
            for (int r = 0; r < 8; ++r) {
                if (lr0 + r < rows) {
                    float4 f = sfr[(lr0 + r) * (FEAT / 4) + k4];
                    acc[r] = fmaf(f.x, w0, acc[r]);
                    acc[r] = fmaf(f.y, w1, acc[r]);
                    acc[r] = fmaf(f.z, w2, acc[r]);
                    acc[r] = fmaf(f.w, w3, acc[r]);
                }
            }
        }
        for (int r = 0; r < 8; ++r) {
            int gr = R0 + lr0 + r;
            if (lr0 + r < rows) {
                float scale = rsqrtf(fmaxf((float)g_deg_src[gr], 1.0f));
                g_tmp[(size_t)gr * OUTF + lane] = acc[r] * scale;
            }
        }
    }
}

// ---------------------------------------------------------------------------
// 6) gather-sum: warp-per-dst, 4 edges/iter x2 unroll, float4 lanes.
// ---------------------------------------------------------------------------
__global__ void gather_kernel(float* __restrict__ out, int n_nodes) {
    int warp_global = (blockIdx.x * blockDim.x + threadIdx.x) >> 5;
    if (warp_global >= n_nodes) return;
    int lane = threadIdx.x & 31;
    int g = lane >> 3;
    int c = lane & 7;

    int beg = g_row_off[warp_global];
    int end = g_row_off[warp_global + 1];

    const float4* tmp4 = reinterpret_cast<const float4*>(g_tmp);
    float4 acc = make_float4(0.f, 0.f, 0.f, 0.f);

    for (int base = beg; base < end; base += 8) {
        int e0 = base + g;
        int e1 = base + 4 + g;
        float4 v0 = make_float4(0.f, 0.f, 0.f, 0.f);
        float4 v1 = make_float4(0.f, 0.f, 0.f, 0.f);
        if (e0 < end) {
            int s = __ldg(&g_csr_src[e0]);
            v0 = tmp4[(size_t)s * 8 + c];
        }
        if (e1 < end) {
            int s = __ldg(&g_csr_src[e1]);
            v1 = tmp4[(size_t)s * 8 + c];
        }
        acc.x += v0.x + v1.x;
        acc.y += v0.y + v1.y;
        acc.z += v0.z + v1.z;
        acc.w += v0.w + v1.w;
    }

#pragma unroll
    for (int off = 8; off < 32; off <<= 1) {
        acc.x += __shfl_xor_sync(0xffffffffu, acc.x, off);
        acc.y += __shfl_xor_sync(0xffffffffu, acc.y, off);
        acc.z += __shfl_xor_sync(0xffffffffu, acc.z, off);
        acc.w += __shfl_xor_sync(0xffffffffu, acc.w, off);
    }

    if (lane < 8) {
        float scale = rsqrtf(fmaxf((float)(end - beg), 1.0f));
        float4 o = make_float4(acc.x * scale, acc.y * scale,
                               acc.z * scale, acc.w * scale);
        reinterpret_cast<float4*>(out)[(size_t)warp_global * 8 + lane] = o;
    }
}

// ---------------------------------------------------------------------------
extern "C" void kernel_launch(void* const* d_in, const int* in_sizes, int n_in,
                              void* d_out, int out_size) {
    const float* feat = (const float*)d_in[0];
    const int*   src  = (const int*)d_in[1];
    const int*   dst  = (const int*)d_in[2];
    const float* W    = (const float*)d_in[3];
    float* out = (float*)d_out;

    int n_nodes = in_sizes[0] / FEAT;
    int E       = in_sizes[1];
    int nb      = (n_nodes + SCAN_B - 1) / SCAN_B;
    int eth8    = (E + 7) / 8;             // edge-octet threads

    // lazily-created side stream + fork/join events (host-side only; no
    // device allocation). Graph capture supports fork-join via events.
    static cudaStream_t s_side = nullptr;
    static cudaEvent_t  ev_fork = nullptr, ev_join = nullptr;
    if (s_side == nullptr) {
        cudaStreamCreateWithFlags(&s_side, cudaStreamNonBlocking);
        cudaEventCreateWithFlags(&ev_fork, cudaEventDisableTiming);
        cudaEventCreateWithFlags(&ev_join, cudaEventDisableTiming);
    }

    init_kernel<<<(n_nodes + 255) / 256, 256>>>(n_nodes);
    degree_kernel<<<(eth8 + 255) / 256, 256>>>(src, dst, E);

    // fork: gemm depends only on degrees (g_deg_src)
    cudaEventRecord(ev_fork, 0);
    cudaStreamWaitEvent(s_side, ev_fork, 0);
    gemm_kernel<<<(n_nodes + RPB - 1) / RPB, 256, 0, s_side>>>(feat, W, n_nodes);
    cudaEventRecord(ev_join, s_side);

    // main stream: scan -> fill (concurrent with gemm)
    scan_kernel<<<nb, SCAN_B>>>(n_nodes);
    fill_kernel<<<(eth8 + 255) / 256, 256>>>(src, dst, E);

    // join: gather needs both fill (CSR) and gemm (g_tmp)
    cudaStreamWaitEvent(0, ev_join, 0);
    gather_kernel<<<(n_nodes * 32 + 255) / 256, 256>>>(out, n_nodes);
}